// round 7
// baseline (speedup 1.0000x reference)
#include <cuda_runtime.h>
#include <cuda_bf16.h>
#include <cstdint>

// lstm_model_8873402433789 R7 — mma.sync bf16 LSTM, single-barrier steps.
// 128 CTAs x 64 rows, 8 warps: (mg unit-half, ng row-quarter). Double-buffered
// h (one pair barrier/step); warp-private double-buffered x staging so the 24
// x-MMAs issue pre-barrier; x-ldsm(t+1) hoisted above the MUFU update.

#define TT 200
#define ROWS 64
#define DD 60
#define KSW 104      // weight smem row stride (bf16 elems)
#define HSTR 136     // h row stride: buf0 [hi 0-31|lo 32-63] buf1 [64-127] pad
#define XSTR 72      // private x row stride: buf0 [hi 0-15|lo 16-31] buf1 [32-63] pad
#define HBYTES (ROWS * HSTR * 2)            // 17408
#define SMEM_BYTES (HBYTES + 8 * 16 * XSTR * 2)  // + 18432 = 35840

static __device__ __forceinline__ uint32_t s2u(const void* p) {
    uint32_t a;
    asm("{ .reg .u64 t; cvta.to.shared.u64 t, %1; cvt.u32.u64 %0, t; }"
        : "=r"(a) : "l"(p));
    return a;
}
static __device__ __forceinline__ float bhi(float a) {
    return __bfloat162float(__float2bfloat16_rn(a));
}
static __device__ __forceinline__ uint32_t bpack(float a, float b) {
    __nv_bfloat162 t = __float22bfloat162_rn(make_float2(a, b));
    return *(uint32_t*)&t;
}
static __device__ __forceinline__ float ex2n(float g) {   // exp(-g)
    float e;
    asm("ex2.approx.f32 %0, %1;" : "=f"(e) : "f"(-1.4426950408889634f * g));
    return e;
}
static __device__ __forceinline__ float frcp(float a) {
    float r;
    asm("rcp.approx.f32 %0, %1;" : "=f"(r) : "f"(a));
    return r;
}
static __device__ __forceinline__ void ldsm4(uint32_t* r, uint32_t addr) {
    asm volatile("ldmatrix.sync.aligned.m8n8.x4.shared.b16 {%0,%1,%2,%3}, [%4];"
                 : "=r"(r[0]), "=r"(r[1]), "=r"(r[2]), "=r"(r[3]) : "r"(addr));
}
static __device__ __forceinline__ void mma16816(float* d, const uint32_t* a,
                                                const uint32_t* b) {
    asm volatile(
        "mma.sync.aligned.m16n8k16.row.col.f32.bf16.bf16.f32 "
        "{%0,%1,%2,%3}, {%4,%5,%6,%7}, {%8,%9}, {%0,%1,%2,%3};"
        : "+f"(d[0]), "+f"(d[1]), "+f"(d[2]), "+f"(d[3])
        : "r"(a[0]), "r"(a[1]), "r"(a[2]), "r"(a[3]), "r"(b[0]), "r"(b[1]));
}

__global__ void __launch_bounds__(256, 1) lstm_mma3_kernel(
    const float* __restrict__ x,  const float* __restrict__ W,
    const float* __restrict__ U,  const float* __restrict__ b,
    const float* __restrict__ W1, const float* __restrict__ b1,
    const float* __restrict__ W2, const float* __restrict__ b2,
    float* __restrict__ out)
{
    __shared__ __align__(16) char SMEM[SMEM_BYTES];
    __nv_bfloat16* wsm = (__nv_bfloat16*)SMEM;            // init-phase weights
    __nv_bfloat16* hsm = (__nv_bfloat16*)SMEM;            // loop: h [64][HSTR]
    __nv_bfloat16* xpr = (__nv_bfloat16*)(SMEM + HBYTES); // loop: x [8w][16][XSTR]

    const int tid = threadIdx.x;
    const int l   = tid & 31;
    const int w   = tid >> 5;
    const int gid = l >> 2, tig = l & 3;
    const int mg  = w & 1;        // unit half
    const int ng  = w >> 1;       // row quarter == pair id

    // ---- phase 1: weights -> wsm  [Uhi 0-31 | Ulo 32-63 | Whi 64-79 | Wlo 80-95]
    for (int idx = tid; idx < 128 * 96; idx += 256) {
        int g = idx / 96, k = idx - g * 96;
        float v;
        if (k < 32)      v = bhi(U[k * 128 + g]);
        else if (k < 64) { float u = U[(k - 32) * 128 + g]; v = u - bhi(u); }
        else if (k < 80) v = bhi(W[(k - 64) * 128 + g]);
        else             { float t = W[(k - 80) * 128 + g]; v = t - bhi(t); }
        wsm[g * KSW + k] = __float2bfloat16_rn(v);
    }
    __syncthreads();

    // ---- A fragments: afr[mt][ks 0..5][4]  (Uhi:0,1 Ulo:2,3 Whi:4 Wlo:5)
    const uint32_t wsmu = s2u(wsm);
    uint32_t afr[4][6][4];
    {
        int laneRow = (l & 7) + 8 * ((l >> 3) & 1);
        int laneK   = 8 * (l >> 4);
#pragma unroll
        for (int mt = 0; mt < 4; ++mt) {
            int Gmt = 32 * mt + 16 * mg;
#pragma unroll
            for (int ks = 0; ks < 6; ++ks)
                ldsm4(afr[mt][ks], wsmu + ((Gmt + laneRow) * KSW + 16 * ks + laneK) * 2);
        }
    }
    float bv[4][2];
#pragma unroll
    for (int mt = 0; mt < 4; ++mt) {
        bv[mt][0] = b[32 * mt + 16 * mg + gid];
        bv[mt][1] = b[32 * mt + 16 * mg + gid + 8];
    }
    __syncthreads();   // wsm dead; SMEM becomes h + x regions

    // ---- phase 2 init: zero h buf0, stage x(0) privately, prefetch x(1)
    for (int idx = tid; idx < ROWS * 64; idx += 256) {
        int rr = idx >> 6, cc = idx & 63;
        hsm[rr * HSTR + cc] = __float2bfloat16_rn(0.0f);
    }
    // lane -> (local row l>>1, feature segment l&1 covering 8 features)
    const int prow = l >> 1, pseg = l & 1;
    const float4* xg = (const float4*)(x +
        ((size_t)blockIdx.x * ROWS + 16 * ng + prow) * (TT * 16) + pseg * 8);
    __nv_bfloat16* xmy = xpr + (w * 16 + prow) * XSTR;
    {
        float4 v0 = xg[0], v1 = xg[1];   // x(0)
        *(uint4*)(xmy + pseg * 8) =
            make_uint4(bpack(v0.x, v0.y), bpack(v0.z, v0.w),
                       bpack(v1.x, v1.y), bpack(v1.z, v1.w));
        *(uint4*)(xmy + 16 + pseg * 8) =
            make_uint4(bpack(v0.x - bhi(v0.x), v0.y - bhi(v0.y)),
                       bpack(v0.z - bhi(v0.z), v0.w - bhi(v0.w)),
                       bpack(v1.x - bhi(v1.x), v1.y - bhi(v1.y)),
                       bpack(v1.z - bhi(v1.z), v1.w - bhi(v1.w)));
    }
    float4 pf0 = xg[4], pf1 = xg[5];     // x(1)
    __syncthreads();

    const uint32_t hbu = s2u(hsm);
    const uint32_t xbu = s2u(xpr + w * 16 * XSTR);
    // ldsm lane addressing pieces
    const int lr8 = l & 7, lq = (l >> 3) & 3;
    // x frag base (per nt handled at call): row nt*8+lr8, col qbuf*32 + lq*8
    // h frag base: row 16ng + nt*8 + lr8, col pbuf*64 + reg*32 + lq*8
    const int bar = 1 + ng;

    // xf(0)
    uint32_t xf[2][4];
    ldsm4(xf[0], xbu + ((0 * 8 + lr8) * XSTR + lq * 8) * 2);
    ldsm4(xf[1], xbu + ((1 * 8 + lr8) * XSTR + lq * 8) * 2);

    float cst[2][2][2], hrg[2][2][2];
#pragma unroll
    for (int i = 0; i < 2; ++i)
#pragma unroll
        for (int j = 0; j < 2; ++j)
#pragma unroll
            for (int k = 0; k < 2; ++k) { cst[i][j][k] = 0.0f; hrg[i][j][k] = 0.0f; }

#pragma unroll 1
    for (int t = 0; t < TT; ++t) {
        const int p = t & 1, pn = p ^ 1;

        // ---- x-MMAs (pre-barrier: only needs private xf)
        float dac[4][2][4];
#pragma unroll
        for (int mt = 0; mt < 4; ++mt)
#pragma unroll
            for (int nt = 0; nt < 2; ++nt) {
                dac[mt][nt][0] = bv[mt][0]; dac[mt][nt][1] = bv[mt][0];
                dac[mt][nt][2] = bv[mt][1]; dac[mt][nt][3] = bv[mt][1];
            }
#pragma unroll
        for (int mt = 0; mt < 4; ++mt)
#pragma unroll
            for (int nt = 0; nt < 2; ++nt) {
                float* d = dac[mt][nt];
                mma16816(d, afr[mt][4], &xf[nt][0]);   // Whi . x_hi
                mma16816(d, afr[mt][4], &xf[nt][2]);   // Whi . x_lo
                mma16816(d, afr[mt][5], &xf[nt][0]);   // Wlo . x_hi
            }

        // ---- pair barrier: h(t) from both warps visible
        asm volatile("bar.sync %0, %1;" :: "r"(bar), "r"(64) : "memory");

        // ---- h fragments from buf p
        uint32_t bhh[2][4], bhl[2][4];
#pragma unroll
        for (int nt = 0; nt < 2; ++nt) {
            uint32_t rowoff = ((16 * ng + nt * 8 + lr8) * HSTR + p * 64 + lq * 8) * 2;
            ldsm4(bhh[nt], hbu + rowoff);            // hi k0-31
            ldsm4(bhl[nt], hbu + rowoff + 64);       // lo k32-63 (+32 elems)
        }
#pragma unroll
        for (int mt = 0; mt < 4; ++mt)
#pragma unroll
            for (int nt = 0; nt < 2; ++nt) {
                float* d = dac[mt][nt];
                mma16816(d, afr[mt][0], &bhh[nt][0]);  // Uhi . h_hi
                mma16816(d, afr[mt][1], &bhh[nt][2]);
                mma16816(d, afr[mt][0], &bhl[nt][0]);  // Uhi . h_lo
                mma16816(d, afr[mt][1], &bhl[nt][2]);
                mma16816(d, afr[mt][2], &bhh[nt][0]);  // Ulo . h_hi
                mma16816(d, afr[mt][3], &bhh[nt][2]);
            }

        // ---- stage x(t+1) into private buf pn; prefetch x(t+2); ldsm xf(t+1)
        {
            *(uint4*)(xmy + pn * 32 + pseg * 8) =
                make_uint4(bpack(pf0.x, pf0.y), bpack(pf0.z, pf0.w),
                           bpack(pf1.x, pf1.y), bpack(pf1.z, pf1.w));
            *(uint4*)(xmy + pn * 32 + 16 + pseg * 8) =
                make_uint4(bpack(pf0.x - bhi(pf0.x), pf0.y - bhi(pf0.y)),
                           bpack(pf0.z - bhi(pf0.z), pf0.w - bhi(pf0.w)),
                           bpack(pf1.x - bhi(pf1.x), pf1.y - bhi(pf1.y)),
                           bpack(pf1.z - bhi(pf1.z), pf1.w - bhi(pf1.w)));
            int tn = (t + 2 < TT) ? t + 2 : TT - 1;
            pf0 = xg[tn * 4]; pf1 = xg[tn * 4 + 1];
            __syncwarp();
            ldsm4(xf[0], xbu + ((0 * 8 + lr8) * XSTR + pn * 32 + lq * 8) * 2);
            ldsm4(xf[1], xbu + ((1 * 8 + lr8) * XSTR + pn * 32 + lq * 8) * 2);
        }

        // ---- state update (batched-rcp sigmoid) + h writeback to buf pn
#pragma unroll
        for (int h = 0; h < 2; ++h) {
            const int u = 16 * mg + gid + 8 * h;
#pragma unroll
            for (int nt = 0; nt < 2; ++nt)
#pragma unroll
                for (int q = 0; q < 2; ++q) {
                    const int e = 2 * h + q;
                    float a  = 1.0f + ex2n(dac[0][nt][e]);
                    float bb = 1.0f + ex2n(dac[1][nt][e]);
                    float cq = 1.0f + ex2n(dac[3][nt][e]);
                    float ab = a * bb, bc = bb * cq, ac = a * cq;
                    float r  = frcp(ab * cq);
                    float si = bc * r, sf = ac * r, so = ab * r;
                    float cc = fmaxf(dac[2][nt][e], 0.0f);
                    float c  = sf * cst[h][nt][q] + si * cc;
                    cst[h][nt][q] = c;
                    float hv = so * fmaxf(c, 0.0f);
                    hrg[h][nt][q] = hv;
                    int rr = 16 * ng + 8 * nt + 2 * tig + q;
                    float hh = bhi(hv);
                    hsm[rr * HSTR + pn * 64 + u]      = __float2bfloat16_rn(hv);
                    hsm[rr * HSTR + pn * 64 + 32 + u] = __float2bfloat16_rn(hv - hh);
                }
        }
        // no trailing barrier: next iteration's bar.sync covers h visibility
    }

    // ---- output heads
    __syncthreads();
    float* h32 = (float*)(SMEM + HBYTES);   // x region dead: [64][32] fp32
#pragma unroll
    for (int h = 0; h < 2; ++h) {
        const int u = 16 * mg + gid + 8 * h;
#pragma unroll
        for (int nt = 0; nt < 2; ++nt)
#pragma unroll
            for (int q = 0; q < 2; ++q) {
                int rr = 16 * ng + 8 * nt + 2 * tig + q;
                h32[rr * 32 + u] = hrg[h][nt][q];
            }
    }
    __syncthreads();

    for (int idx = tid; idx < ROWS * DD; idx += 256) {
        int rr = idx / DD, d = idx - rr * DD;
        const float* hr = h32 + rr * 32;
        float aL = b1[d], aA = b2[d];
#pragma unroll
        for (int u = 0; u < 32; ++u) {
            float hu = hr[u];
            aL = fmaf(hu, W1[u * DD + d], aL);
            aA = fmaf(hu, W2[u * DD + d], aA);
        }
        size_t grow = (size_t)blockIdx.x * ROWS + rr;
        out[grow * DD + d] = aL;
        out[(8192 + grow) * DD + d] = aA;
    }
}

extern "C" void kernel_launch(void* const* d_in, const int* in_sizes, int n_in,
                              void* d_out, int out_size) {
    const float* x  = (const float*)d_in[0];
    const float* W  = (const float*)d_in[1];
    const float* U  = (const float*)d_in[2];
    const float* b  = (const float*)d_in[3];
    const float* W1 = (const float*)d_in[4];
    const float* b1 = (const float*)d_in[5];
    const float* W2 = (const float*)d_in[6];
    const float* b2 = (const float*)d_in[7];
    float* out = (float*)d_out;

    lstm_mma3_kernel<<<128, 256>>>(x, W, U, b, W1, b1, W2, b2, out);
}